// round 9
// baseline (speedup 1.0000x reference)
#include <cuda_runtime.h>
#include <cuda_fp16.h>
#include <math.h>
#include <stdint.h>

#define N_NODES 100000
#define N_EDGES 1600000
#define D 64
#define NP 4160              // 64*64+64
#define R3 12480             // 3*NP
#define TOPK 32
#define SCAP 4096

// ---------------- scratch (zero-initialized at module load) ----------------
__device__ float g_y[N_NODES];
__device__ int   g_hist[2048];
__device__ __align__(16) float g_zflat[2048];
__device__ float g_gi[R3];
__device__ float g_gh[2][R3];
__device__ __align__(16) float g_neww[NP];
__device__ __align__(128) float  g_xw[(size_t)N_NODES * D];    // layer-0 gather operand (fp32: feeds topk)
__device__ __align__(128) __half g_xwh[(size_t)N_NODES * D];   // layer-1 gather operand (fp16: final out only)
__device__ __align__(128) float g_h1[(size_t)N_NODES * D];
__device__ int   g_indeg[N_NODES];
__device__ float g_dinv[N_NODES];
__device__ int   g_rowptr[N_NODES];
__device__ int   g_rowend[N_NODES];
__device__ int   g_cursor[N_NODES];
__device__ int2  g_csre[N_EDGES];
__device__ int   g_total;

__device__ __forceinline__ float wredf(float v) {
    #pragma unroll
    for (int o = 16; o; o >>= 1) v += __shfl_xor_sync(0xffffffffu, v, o);
    return v;
}
__device__ __forceinline__ unsigned fflip(float v) {
    unsigned u = __float_as_uint(v);
    return (u & 0x80000000u) ? ~u : (u | 0x80000000u);
}
__device__ __forceinline__ float funflip(unsigned k) {
    unsigned u = (k & 0x80000000u) ? (k & 0x7fffffffu) : ~k;
    return __uint_as_float(u);
}

// ---------------- CSR build (indeg/g_total self-reset by k_gat<1>) ----------------
__global__ void k_deg(const int* __restrict__ dst) {
    int e = blockIdx.x * 256 + threadIdx.x;
    if (e < N_EDGES) atomicAdd(&g_indeg[dst[e]], 1);
}

__global__ void k_alloc() {
    __shared__ int ws[32];
    __shared__ int base;
    int t = threadIdx.x;                  // 1024
    int i = blockIdx.x * 1024 + t;
    int lane = t & 31, wid = t >> 5;
    int v = (i < N_NODES) ? g_indeg[i] : 0;
    if (i < N_NODES) g_dinv[i] = rsqrtf((float)(v + 1));
    int x = v;
    #pragma unroll
    for (int o = 1; o < 32; o <<= 1) {
        int y = __shfl_up_sync(0xffffffffu, x, o);
        if (lane >= o) x += y;
    }
    if (lane == 31) ws[wid] = x;
    __syncthreads();
    if (wid == 0) {
        int s = ws[lane];
        #pragma unroll
        for (int o = 1; o < 32; o <<= 1) {
            int y = __shfl_up_sync(0xffffffffu, s, o);
            if (lane >= o) s += y;
        }
        ws[lane] = s;
        if (lane == 31) base = atomicAdd(&g_total, s);
    }
    __syncthreads();
    if (i < N_NODES) {
        int rp = base + ((wid > 0) ? ws[wid - 1] : 0) + x - v;
        g_rowptr[i] = rp;
        g_rowend[i] = rp + v;
        g_cursor[i] = rp;
    }
}

__global__ void k_fill(const int* __restrict__ src, const int* __restrict__ dst) {
    int e = blockIdx.x * 256 + threadIdx.x;
    if (e < N_EDGES) {
        int d = dst[e];
        int s = src[e];
        int pos = atomicAdd(&g_cursor[d], 1);
        g_csre[pos] = make_int2(s, __float_as_int(g_dinv[s]));
    }
}

// ---------------- y0 (hist reset by previous call's k_sel / zero-init) ----------------
__global__ void k_y0(const float* __restrict__ x, const float* __restrict__ p) {
    __shared__ __align__(16) float pn[64];
    __shared__ float sp[65];
    int t = threadIdx.x;   // 1024
    if (t < 64) sp[t] = p[t];
    __syncthreads();
    if (t < 32) {
        float v = sp[2 * t] * sp[2 * t] + sp[2 * t + 1] * sp[2 * t + 1];
        v = wredf(v);
        if (t == 0) sp[64] = sqrtf(v) + 1e-8f;
    }
    __syncthreads();
    if (t < 64) pn[t] = sp[t] / sp[64];
    __syncthreads();
    int node = blockIdx.x * 32 + (t >> 5);
    int lane = t & 31;
    if (node < N_NODES) {
        float2 hv = ((const float2*)(x + (size_t)node * D))[lane];
        float v = hv.x * pn[2 * lane] + hv.y * pn[2 * lane + 1];
        v = wredf(v);
        if (lane == 0) {
            g_y[node] = v;
            atomicAdd(&g_hist[fflip(v) >> 21], 1);
        }
    }
}

// ---------------- sel: threshold + collect + exact top-32 + zflat + hist reset ----------------
__global__ void k_sel(const float* __restrict__ hx, int use_h1) {
    const float* h = use_h1 ? g_h1 : hx;
    __shared__ int s[2048];
    __shared__ unsigned long long scand[SCAP];
    __shared__ int selI[TOPK];
    __shared__ float tw[TOPK];
    __shared__ int thr_s, cnt;
    int t = threadIdx.x;   // 1024
    int lane = t & 31, wid = t >> 5;
    s[t] = g_hist[t]; s[t + 1024] = g_hist[t + 1024];
    if (t == 0) cnt = 0;
    __syncthreads();
    for (int off = 1; off < 2048; off <<= 1) {
        int a0 = (t + off < 2048) ? s[t + off] : 0;
        int a1 = (t + 1024 + off < 2048) ? s[t + 1024 + off] : 0;
        __syncthreads();
        s[t] += a0; s[t + 1024] += a1;
        __syncthreads();
    }
    int b0 = t, b1 = t + 1024;
    if (s[b0] >= TOPK && (b0 == 2047 || s[b0 + 1] < TOPK)) thr_s = b0;
    if (s[b1] >= TOPK && (b1 == 2047 || s[b1 + 1] < TOPK)) thr_s = b1;
    __syncthreads();
    int thr = thr_s;
    for (int i = t; i < N_NODES; i += 1024) {
        float v = g_y[i];
        if ((int)(fflip(v) >> 21) >= thr) {
            int pos = atomicAdd(&cnt, 1);
            if (pos < SCAP)
                scand[pos] = ((unsigned long long)fflip(v) << 32)
                           | (unsigned)(~(unsigned)i);
        }
    }
    __syncthreads();
    int nc = min(cnt, SCAP);
    if (wid == 0) {
        for (int k = 0; k < TOPK; k++) {
            unsigned long long best = 0ull; int bslot = -1;
            for (int j = lane; j < nc; j += 32) {
                unsigned long long kk = scand[j];
                if (kk > best) { best = kk; bslot = j; }
            }
            unsigned long long lb = best;
            #pragma unroll
            for (int o = 16; o; o >>= 1) {
                unsigned long long ok = __shfl_xor_sync(0xffffffffu, best, o);
                if (ok > best) best = ok;
            }
            if (lb == best && bslot >= 0) scand[bslot] = 0ull;
            if (lane == 0) {
                selI[k] = (int)(~(unsigned)(best & 0xffffffffu));
                tw[k] = tanhf(funflip((unsigned)(best >> 32)));
            }
        }
    }
    __syncthreads();
    for (int idx = t; idx < 2048; idx += 1024) {
        int k = idx & 31, d = idx >> 5;
        g_zflat[idx] = h[(size_t)selI[k] * D + d] * tw[k];
    }
    g_hist[t] = 0; g_hist[t + 1024] = 0;
}

// ---------------- GRU mat-vecs ----------------
__global__ void k_mv_gi(const float* __restrict__ wih) {
    __shared__ __align__(16) float zs[2048];
    int t = threadIdx.x;  // 256
    int lane = t & 31, warp = t >> 5;
    for (int j = t; j < 2048; j += 256) zs[j] = g_zflat[j];
    __syncthreads();
    const float4* zs4 = (const float4*)zs;
    int row = blockIdx.x * 8 + warp;
    const float4* r = (const float4*)(wih + (size_t)row * 2048);
    float4 A = make_float4(0.f, 0.f, 0.f, 0.f);
    #pragma unroll 8
    for (int j = lane; j < 512; j += 32) {
        float4 a = __ldcs(r + j), xb = zs4[j];
        A.x += a.x * xb.x; A.y += a.y * xb.y;
        A.z += a.z * xb.z; A.w += a.w * xb.w;
    }
    float v = wredf((A.x + A.y) + (A.z + A.w));
    if (lane == 0) g_gi[row] = v;
}

__global__ void k_mv_gh(const float* __restrict__ whh, const float* __restrict__ w,
                        const float* __restrict__ b, int layer) {
    __shared__ __align__(16) float hs[NP];
    int t = threadIdx.x;  // 256
    int lane = t & 31, warp = t >> 5;
    for (int j = t; j < 4096; j += 256) hs[j] = w[j];
    if (t < 64) hs[4096 + t] = b[t];
    __syncthreads();
    const float4* hs4 = (const float4*)hs;
    int row = blockIdx.x * 8 + warp;
    const float4* r = (const float4*)(whh + (size_t)row * NP);
    float4 A = make_float4(0.f, 0.f, 0.f, 0.f);
    #pragma unroll 8
    for (int j = lane; j < 1040; j += 32) {
        float4 a = __ldcs(r + j), xb = hs4[j];
        A.x += a.x * xb.x; A.y += a.y * xb.y;
        A.z += a.z * xb.z; A.w += a.w * xb.w;
    }
    float v = wredf((A.x + A.y) + (A.z + A.w));
    if (lane == 0) g_gh[layer][row] = v;
}

// ---------------- gates ----------------
__global__ void k_gate(const float* __restrict__ bih, const float* __restrict__ bhh,
                       const float* __restrict__ w,   const float* __restrict__ b, int layer) {
    int u = blockIdx.x * 256 + threadIdx.x;
    if (u >= NP) return;
    const float* gh = g_gh[layer];
    float hv = (u < 4096) ? w[u] : b[u - 4096];
    float ir = g_gi[u] + bih[u],               hr = gh[u] + bhh[u];
    float iz = g_gi[NP + u] + bih[NP + u],     hz = gh[NP + u] + bhh[NP + u];
    float in = g_gi[2*NP + u] + bih[2*NP + u], hn = gh[2*NP + u] + bhh[2*NP + u];
    float r = 1.f / (1.f + expf(-(ir + hr)));
    float z = 1.f / (1.f + expf(-(iz + hz)));
    float n = tanhf(in + r * hn);
    g_neww[u] = (1.f - z) * n + z * hv;
}

// ---------------- xw = h @ W^T (OUT16: fp16 for final layer, fp32 otherwise) ----------------
template<int OUT16>
__global__ void k_xw(const float* __restrict__ hx, int use_h1) {
    const float* h = use_h1 ? g_h1 : hx;
    __shared__ __align__(16) float hsT[64 * 64];
    __shared__ __align__(16) float wsT[64 * 64];
    int t = threadIdx.x;  // 256
    int base = blockIdx.x * 64;
    for (int idx = t; idx < 4096; idx += 256) {
        int n = idx >> 6, d = idx & 63;
        int node = base + n;
        hsT[d * 64 + n] = (node < N_NODES) ? h[(size_t)node * D + d] : 0.f;
    }
    for (int idx = t; idx < 4096; idx += 256) {
        int o = idx >> 6, d = idx & 63;
        wsT[d * 64 + o] = g_neww[idx];
    }
    __syncthreads();
    int tx = t & 15, ty = t >> 4;
    float acc[4][4];
    #pragma unroll
    for (int i = 0; i < 4; i++)
        #pragma unroll
        for (int j = 0; j < 4; j++) acc[i][j] = 0.f;
    #pragma unroll 4
    for (int d = 0; d < 64; d++) {
        float4 a = *(const float4*)&hsT[d * 64 + ty * 4];
        float4 b = *(const float4*)&wsT[d * 64 + tx * 4];
        float av[4] = {a.x, a.y, a.z, a.w};
        float bvv[4] = {b.x, b.y, b.z, b.w};
        #pragma unroll
        for (int i = 0; i < 4; i++)
            #pragma unroll
            for (int j = 0; j < 4; j++) acc[i][j] += av[i] * bvv[j];
    }
    #pragma unroll
    for (int i = 0; i < 4; i++) {
        int node = base + ty * 4 + i;
        if (node < N_NODES) {
            if (OUT16) {
                __half2 h2a = __floats2half2_rn(acc[i][0], acc[i][1]);
                __half2 h2b = __floats2half2_rn(acc[i][2], acc[i][3]);
                ((__half2*)(g_xwh + (size_t)node * D))[tx * 2]     = h2a;
                ((__half2*)(g_xwh + (size_t)node * D))[tx * 2 + 1] = h2b;
            } else {
                ((float4*)(g_xw + (size_t)node * D))[tx] =
                    make_float4(acc[i][0], acc[i][1], acc[i][2], acc[i][3]);
            }
        }
    }
}

// ---------------- GCN aggregation ----------------
// MODE 0: fp32 operand, relu, writes g_h1 + fused y1/hist. MODE 1: fp16 operand, writes out + self-reset.
template<int MODE>
__global__ void k_gat(float* __restrict__ outp, const float* __restrict__ p) {
    __shared__ __align__(16) float pn[64];
    __shared__ float sp[65];
    int t = threadIdx.x;  // 256
    if (MODE == 0) {
        if (t < 64) sp[t] = p[t];
        __syncthreads();
        if (t < 32) {
            float v = sp[2 * t] * sp[2 * t] + sp[2 * t + 1] * sp[2 * t + 1];
            v = wredf(v);
            if (t == 0) sp[64] = sqrtf(v) + 1e-8f;
        }
        __syncthreads();
        if (t < 64) pn[t] = sp[t] / sp[64];
        __syncthreads();
    }
    int i = blockIdx.x * 8 + (t >> 5);
    int lane = t & 31;
    if (i >= N_NODES) return;
    float di = g_dinv[i];
    float2 bb = ((const float2*)(g_neww + 4096))[lane];
    float2 xi, nb = make_float2(0.f, 0.f);
    if (MODE == 0) xi = ((const float2*)(g_xw + (size_t)i * D))[lane];
    else           xi = __half22float2(((const __half2*)(g_xwh + (size_t)i * D))[lane]);
    int s0 = g_rowptr[i], s1 = g_rowend[i];
    #pragma unroll 4
    for (int j = s0; j < s1; j++) {
        int2 e = __ldg(&g_csre[j]);
        float2 v;
        if (MODE == 0) v = ((const float2*)(g_xw + (size_t)e.x * D))[lane];
        else           v = __half22float2(((const __half2*)(g_xwh + (size_t)e.x * D))[lane]);
        float wv = __int_as_float(e.y);
        nb.x += wv * v.x;
        nb.y += wv * v.y;
    }
    float2 acc;
    acc.x = bb.x + di * (di * xi.x + nb.x);
    acc.y = bb.y + di * (di * xi.y + nb.y);
    if (MODE == 0) {
        acc.x = fmaxf(acc.x, 0.f);
        acc.y = fmaxf(acc.y, 0.f);
        ((float2*)(g_h1 + (size_t)i * D))[lane] = acc;
        float v = acc.x * pn[2 * lane] + acc.y * pn[2 * lane + 1];
        v = wredf(v);
        if (lane == 0) {
            g_y[i] = v;
            atomicAdd(&g_hist[fflip(v) >> 21], 1);
        }
    } else {
        ((float2*)(outp + (size_t)i * D))[lane] = acc;
        if (lane == 0) {
            g_indeg[i] = 0;
            if (i == 0) g_total = 0;
        }
    }
}

// ---------------- stream resources ----------------
struct HxRes {
    cudaStream_t sB = nullptr, sC = nullptr;
    cudaEvent_t evFork = nullptr, evGH0 = nullptr, evGH1 = nullptr, evCSR = nullptr;
    bool ok = false;
    HxRes() {
        ok = (cudaStreamCreateWithFlags(&sB, cudaStreamNonBlocking) == cudaSuccess) &&
             (cudaStreamCreateWithFlags(&sC, cudaStreamNonBlocking) == cudaSuccess) &&
             (cudaEventCreateWithFlags(&evFork, cudaEventDisableTiming) == cudaSuccess) &&
             (cudaEventCreateWithFlags(&evGH0, cudaEventDisableTiming) == cudaSuccess) &&
             (cudaEventCreateWithFlags(&evGH1, cudaEventDisableTiming) == cudaSuccess) &&
             (cudaEventCreateWithFlags(&evCSR, cudaEventDisableTiming) == cudaSuccess);
    }
};
static HxRes hx;

// ---------------- launch ----------------
extern "C" void kernel_launch(void* const* d_in, const int* in_sizes, int n_in,
                              void* d_out, int out_size) {
    const float* x    = (const float*)d_in[0];
    const int*   ei   = (const int*)d_in[1];
    const float* p0   = (const float*)d_in[2];
    const float* p1   = (const float*)d_in[3];
    const float* w0   = (const float*)d_in[4];
    const float* b0   = (const float*)d_in[5];
    const float* w1   = (const float*)d_in[6];
    const float* b1   = (const float*)d_in[7];
    const float* wih0 = (const float*)d_in[8];
    const float* whh0 = (const float*)d_in[9];
    const float* bih0 = (const float*)d_in[10];
    const float* bhh0 = (const float*)d_in[11];
    const float* wih1 = (const float*)d_in[12];
    const float* whh1 = (const float*)d_in[13];
    const float* bih1 = (const float*)d_in[14];
    const float* bhh1 = (const float*)d_in[15];
    float* out = (float*)d_out;

    const int* src = ei;
    const int* dst = ei + N_EDGES;

    bool dual = hx.ok;
    cudaStream_t sA = 0;
    cudaStream_t sB = dual ? hx.sB : sA;
    cudaStream_t sC = dual ? hx.sC : sA;

    if (dual) {
        cudaEventRecord(hx.evFork, sA);
        cudaStreamWaitEvent(sB, hx.evFork, 0);
        cudaStreamWaitEvent(sC, hx.evFork, 0);
    }

    // chain A head
    k_y0<<<(N_NODES + 31) / 32, 1024, 0, sA>>>(x, p0);                  // 0
    k_sel<<<1, 1024, 0, sA>>>(x, 0);                                    // 1
    k_mv_gi<<<R3 / 8, 256, 0, sA>>>(wih0);                              // 2

    // chain B: gh precompute
    k_mv_gh<<<R3 / 8, 256, 0, sB>>>(whh0, w0, b0, 0);                   // 3 <- profiled
    if (dual) cudaEventRecord(hx.evGH0, sB);
    k_mv_gh<<<R3 / 8, 256, 0, sB>>>(whh1, w1, b1, 1);
    if (dual) cudaEventRecord(hx.evGH1, sB);

    // chain C: CSR build
    k_deg<<<(N_EDGES + 255) / 256, 256, 0, sC>>>(dst);
    k_alloc<<<(N_NODES + 1023) / 1024, 1024, 0, sC>>>();
    k_fill<<<(N_EDGES + 255) / 256, 256, 0, sC>>>(src, dst);
    if (dual) cudaEventRecord(hx.evCSR, sC);

    // chain A: layer 0 tail (fp32 gather operand)
    if (dual) cudaStreamWaitEvent(sA, hx.evGH0, 0);
    k_gate<<<(NP + 255) / 256, 256, 0, sA>>>(bih0, bhh0, w0, b0, 0);
    k_xw<0><<<(N_NODES + 63) / 64, 256, 0, sA>>>(x, 0);
    if (dual) cudaStreamWaitEvent(sA, hx.evCSR, 0);
    k_gat<0><<<(N_NODES + 7) / 8, 256, 0, sA>>>(nullptr, p1);

    // chain A: layer 1 (fp16 gather operand -> final out)
    k_sel<<<1, 1024, 0, sA>>>(nullptr, 1);
    k_mv_gi<<<R3 / 8, 256, 0, sA>>>(wih1);
    if (dual) cudaStreamWaitEvent(sA, hx.evGH1, 0);
    k_gate<<<(NP + 255) / 256, 256, 0, sA>>>(bih1, bhh1, w1, b1, 1);
    k_xw<1><<<(N_NODES + 63) / 64, 256, 0, sA>>>(nullptr, 1);
    k_gat<1><<<(N_NODES + 7) / 8, 256, 0, sA>>>(out, nullptr);
}